// round 7
// baseline (speedup 1.0000x reference)
#include <cuda_runtime.h>
#include <math.h>
#include <stdint.h>

#define THREADS 256
#define NBLOCKS 592             // 148 SMs * 4 CTAs (48KB smem bin) = one wave
#define CROWS   512             // rows per chunk
#define INF4    640             // in float4 per chunk  (512*5/4)
#define TGF4    128             // tg float4 per chunk  (512/4)
#define BUFF4   (INF4 + TGF4)   // 768 float4 = 12 KB
#define STAGES  4               // 48 KB: 3 chunks in flight per CTA
#define ERR_OK  0.1f

__device__ float g_partials[NBLOCKS];
__device__ unsigned int g_count = 0;

__device__ __forceinline__ void cp16(uint32_t saddr, const void* gptr) {
    asm volatile("cp.async.cg.shared.global [%0], [%1], 16;\n"
                 :: "r"(saddr), "l"(gptr));
}

__global__ __launch_bounds__(THREADS)
void loss_fused_kernel(const float* __restrict__ in,
                       const float* __restrict__ tg,
                       float* __restrict__ out,
                       int n)
{
    __shared__ float4 sbuf[STAGES][BUFF4];   // 4 * 12 KB = 48 KB
    const int t = threadIdx.x;

    const long long nchunks = (long long)n / CROWS;
    // chunks for this block: c = blockIdx.x + j*gridDim.x  (static -> deterministic)
    const long long m = (nchunks > blockIdx.x)
                      ? (nchunks - 1 - blockIdx.x) / gridDim.x + 1 : 0;

    const uint32_t sb0 = (uint32_t)__cvta_generic_to_shared(&sbuf[0][0]);

    auto issue_chunk = [&](long long j, int stage) {
        const long long c = blockIdx.x + j * (long long)gridDim.x;
        const uint32_t sa = sb0 + (uint32_t)stage * (BUFF4 * 16);
        if (j < m) {
            const float4* gin = (const float4*)(in + c * (CROWS * 5));
            const float4* gtg = (const float4*)(tg + c * CROWS);
            cp16(sa + (uint32_t)t * 16,          gin + t);
            cp16(sa + (uint32_t)(t + 256) * 16,  gin + t + 256);
            if (t < 128) cp16(sa + (uint32_t)(512 + t) * 16, gin + 512 + t);
            else         cp16(sa + (uint32_t)(INF4 + (t - 128)) * 16, gtg + (t - 128));
        }
        asm volatile("cp.async.commit_group;\n" ::: "memory");
    };

    float acc = 0.0f;

    // ---- prologue: 3 chunks in flight ----
    issue_chunk(0, 0);
    issue_chunk(1, 1);
    issue_chunk(2, 2);

    // ---- pipelined main loop: ONE __syncthreads per iteration ----
    for (long long j = 0; j < m; j++) {
        asm volatile("cp.async.wait_group 2;\n" ::: "memory");  // chunk j landed
        __syncthreads();   // chunk j visible block-wide; compute(j-1) done block-wide

        issue_chunk(j + 3, (int)((j + 3) % STAGES));  // buf[(j-1)%4] now free

        const float4* buf = sbuf[j % STAGES];
        if (t < 128) {
            // thread t owns rows 4t..4t+3 of this chunk: floats [20t,20t+20)
            const float4 a0 = buf[5 * t + 0];
            const float4 a1 = buf[5 * t + 1];
            const float4 a2 = buf[5 * t + 2];
            const float4 a3 = buf[5 * t + 3];
            const float4 a4 = buf[5 * t + 4];
            const float4 tv = buf[INF4 + t];

            const float d0 = (fabsf(a1.x - a0.z) < ERR_OK) ? (a0.x - a1.x) : (a0.x - tv.x);
            const float d1 = (fabsf(a2.y - a1.w) < ERR_OK) ? (a1.y - a2.y) : (a1.y - tv.y);
            const float d2 = (fabsf(a3.z - a3.x) < ERR_OK) ? (a2.z - a3.z) : (a2.z - tv.z);
            const float d3 = (fabsf(a4.w - a4.y) < ERR_OK) ? (a3.w - a4.w) : (a3.w - tv.w);

            acc += fabsf(d0) + fabsf(d1) + fabsf(d2) + fabsf(d3);
        }
    }
    asm volatile("cp.async.wait_group 0;\n" ::: "memory");  // drain

    // ---- tail rows [nchunks*CROWS, n): block 0, scalar from global ----
    if (blockIdx.x == 0) {
        for (long long r = nchunks * CROWS + t; r < n; r += THREADS) {
            const float x0 = in[5 * r + 0];
            const float x2 = in[5 * r + 2];
            const float x4 = in[5 * r + 4];
            const float tvv = tg[r];
            const float d = (fabsf(x4 - x2) < ERR_OK) ? (x0 - x4) : (x0 - tvv);
            acc += fabsf(d);
        }
    }

    // ---- deterministic block reduction ----
    __shared__ float red[THREADS];
    __syncthreads();
    red[t] = acc;
    __syncthreads();
    #pragma unroll
    for (int s = THREADS / 2; s >= 32; s >>= 1) {
        if (t < s) red[t] += red[t + s];
        __syncthreads();
    }
    if (t < 32) {
        float v = red[t];
        #pragma unroll
        for (int off = 16; off > 0; off >>= 1)
            v += __shfl_down_sync(0xFFFFFFFFu, v, off);
        if (t == 0) g_partials[blockIdx.x] = v;
    }

    // ---- fused final reduction: last block sums partials (fixed order) ----
    __shared__ bool is_last;
    __threadfence();
    if (t == 0) {
        const unsigned int c = atomicAdd(&g_count, 1u);
        is_last = (c == gridDim.x - 1);
    }
    __syncthreads();

    if (is_last) {
        __threadfence();
        double s = 0.0;
        for (int i = t; i < (int)gridDim.x; i += THREADS)
            s += (double)g_partials[i];
        __shared__ double sd[THREADS];
        sd[t] = s;
        __syncthreads();
        #pragma unroll
        for (int st = THREADS / 2; st > 0; st >>= 1) {
            if (t < st) sd[t] += sd[t + st];
            __syncthreads();
        }
        if (t == 0) {
            out[0] = (float)(sd[0] / (double)n);
            g_count = 0;   // reset for next graph replay
        }
    }
}

extern "C" void kernel_launch(void* const* d_in, const int* in_sizes, int n_in,
                              void* d_out, int out_size)
{
    const float* inputs  = (const float*)d_in[0];   // [N, 5] float32
    const float* targets = (const float*)d_in[1];   // [N, 1] float32
    float* out = (float*)d_out;

    const int n = in_sizes[1];   // N rows

    loss_fused_kernel<<<NBLOCKS, THREADS>>>(inputs, targets, out, n);
}

// round 8
// speedup vs baseline: 1.0441x; 1.0441x over previous
#include <cuda_runtime.h>
#include <math.h>
#include <stdint.h>

#define THREADS 256
#define NBLOCKS 740             // 148 SMs * 5 CTAs (36KB smem bin) = exactly one wave
#define CROWS   512             // rows per chunk
#define INF4    640             // in float4 per chunk  (512*5/4)
#define TGF4    128             // tg float4 per chunk  (512/4)
#define BUFF4   (INF4 + TGF4)   // 768 float4 = 12 KB
#define STAGES  3
#define ERR_OK  0.1f

__device__ float g_partials[NBLOCKS];
__device__ unsigned int g_count = 0;

__device__ __forceinline__ void cp16(uint32_t saddr, const void* gptr) {
    asm volatile("cp.async.cg.shared.global [%0], [%1], 16;\n"
                 :: "r"(saddr), "l"(gptr));
}

__global__ __launch_bounds__(THREADS)
void loss_fused_kernel(const float* __restrict__ in,
                       const float* __restrict__ tg,
                       float* __restrict__ out,
                       int n)
{
    __shared__ float4 sbuf[STAGES][BUFF4];   // 3 * 12 KB = 36 KB
    const int t = threadIdx.x;

    const long long nchunks = (long long)n / CROWS;
    // chunks for this block: c = blockIdx.x + j*gridDim.x  (static -> deterministic)
    const long long m = (nchunks > blockIdx.x)
                      ? (nchunks - 1 - blockIdx.x) / gridDim.x + 1 : 0;

    const uint32_t sb0 = (uint32_t)__cvta_generic_to_shared(&sbuf[0][0]);

    auto issue_chunk = [&](long long j, int stage) {
        const long long c = blockIdx.x + j * (long long)gridDim.x;
        const uint32_t sa = sb0 + (uint32_t)stage * (BUFF4 * 16);
        if (j < m) {
            const float4* gin = (const float4*)(in + c * (CROWS * 5));
            const float4* gtg = (const float4*)(tg + c * CROWS);
            cp16(sa + (uint32_t)t * 16,          gin + t);
            cp16(sa + (uint32_t)(t + 256) * 16,  gin + t + 256);
            if (t < 128) cp16(sa + (uint32_t)(512 + t) * 16, gin + 512 + t);
            else         cp16(sa + (uint32_t)(INF4 + (t - 128)) * 16, gtg + (t - 128));
        }
        asm volatile("cp.async.commit_group;\n" ::: "memory");
    };

    float acc = 0.0f;

    // ---- prologue: 2 chunks in flight ----
    issue_chunk(0, 0);
    issue_chunk(1, 1);

    // ---- pipelined main loop: ONE __syncthreads per iteration ----
    for (long long j = 0; j < m; j++) {
        asm volatile("cp.async.wait_group 1;\n" ::: "memory");  // chunk j landed
        __syncthreads();   // chunk j visible block-wide; compute(j-1) done block-wide

        issue_chunk(j + 2, (int)((j + 2) % STAGES));  // buf[(j-1)%3] now free

        const float4* buf = sbuf[j % STAGES];
        if (t < 128) {
            // thread t owns rows 4t..4t+3 of this chunk: floats [20t,20t+20)
            const float4 a0 = buf[5 * t + 0];
            const float4 a1 = buf[5 * t + 1];
            const float4 a2 = buf[5 * t + 2];
            const float4 a3 = buf[5 * t + 3];
            const float4 a4 = buf[5 * t + 4];
            const float4 tv = buf[INF4 + t];

            const float d0 = (fabsf(a1.x - a0.z) < ERR_OK) ? (a0.x - a1.x) : (a0.x - tv.x);
            const float d1 = (fabsf(a2.y - a1.w) < ERR_OK) ? (a1.y - a2.y) : (a1.y - tv.y);
            const float d2 = (fabsf(a3.z - a3.x) < ERR_OK) ? (a2.z - a3.z) : (a2.z - tv.z);
            const float d3 = (fabsf(a4.w - a4.y) < ERR_OK) ? (a3.w - a4.w) : (a3.w - tv.w);

            acc += fabsf(d0) + fabsf(d1) + fabsf(d2) + fabsf(d3);
        }
    }
    asm volatile("cp.async.wait_group 0;\n" ::: "memory");  // drain

    // ---- tail rows [nchunks*CROWS, n): block 0, scalar from global ----
    if (blockIdx.x == 0) {
        for (long long r = nchunks * CROWS + t; r < n; r += THREADS) {
            const float x0 = in[5 * r + 0];
            const float x2 = in[5 * r + 2];
            const float x4 = in[5 * r + 4];
            const float tvv = tg[r];
            const float d = (fabsf(x4 - x2) < ERR_OK) ? (x0 - x4) : (x0 - tvv);
            acc += fabsf(d);
        }
    }

    // ---- deterministic block reduction ----
    __shared__ float red[THREADS];
    __syncthreads();
    red[t] = acc;
    __syncthreads();
    #pragma unroll
    for (int s = THREADS / 2; s >= 32; s >>= 1) {
        if (t < s) red[t] += red[t + s];
        __syncthreads();
    }
    if (t < 32) {
        float v = red[t];
        #pragma unroll
        for (int off = 16; off > 0; off >>= 1)
            v += __shfl_down_sync(0xFFFFFFFFu, v, off);
        if (t == 0) g_partials[blockIdx.x] = v;
    }

    // ---- fused final reduction: last block sums partials (fixed order) ----
    __shared__ bool is_last;
    __threadfence();
    if (t == 0) {
        const unsigned int c = atomicAdd(&g_count, 1u);
        is_last = (c == gridDim.x - 1);
    }
    __syncthreads();

    if (is_last) {
        __threadfence();
        double s = 0.0;
        for (int i = t; i < (int)gridDim.x; i += THREADS)
            s += (double)g_partials[i];
        __shared__ double sd[THREADS];
        sd[t] = s;
        __syncthreads();
        #pragma unroll
        for (int st = THREADS / 2; st > 0; st >>= 1) {
            if (t < st) sd[t] += sd[t + st];
            __syncthreads();
        }
        if (t == 0) {
            out[0] = (float)(sd[0] / (double)n);
            g_count = 0;   // reset for next graph replay
        }
    }
}

extern "C" void kernel_launch(void* const* d_in, const int* in_sizes, int n_in,
                              void* d_out, int out_size)
{
    const float* inputs  = (const float*)d_in[0];   // [N, 5] float32
    const float* targets = (const float*)d_in[1];   // [N, 1] float32
    float* out = (float*)d_out;

    const int n = in_sizes[1];   // N rows

    loss_fused_kernel<<<NBLOCKS, THREADS>>>(inputs, targets, out, n);
}